// round 12
// baseline (speedup 1.0000x reference)
#include <cuda_runtime.h>
#include <stdint.h>

// MinusSpan: B=16, T=2048, D=1024 (H=512), N_SPANS=256
// out[b,s] = concat(fwd[j]-f_pre, bwd[i]-b_post, f_pre, b_post), zeroed if i==0&&j==0
// f_pre = fwd[i-1] if i>=1 else 0 ; b_post = bwd[j+1] if j+1<T else 0
//
// R12: identical to R11 (best, 10.72us) EXCEPT output stores are __stwt
// (write-through). Theory: default/.cs stores both WRITE-ALLOCATE in L2, so
// 33.5MB/replay of never-read output lines thrash L2 and evict the hot input
// rows. WT keeps output lines out of L2 entirely -> hot read set (~25MB,
// identical indices every graph replay) stays resident, DRAM carries only the
// unavoidable write stream.

static constexpr int Bc = 16;
static constexpr int Tc = 2048;
static constexpr int Dc = 1024;
static constexpr int NS = 256;
static constexpr int D4 = Dc / 4;           // 256 float4 per (b,t) row
static constexpr int H4 = Dc / 8;           // 128 float4 per half-row
static constexpr int NSPAN_TOT = Bc * NS;   // 4096 spans
static constexpr int NSP = 2;               // spans per CTA (MLP 8 / thread)

__global__ __launch_bounds__(128)
void minus_span_kernel(const float* __restrict__ inp,
                       const unsigned int* __restrict__ idxw,  // raw 32-bit view of span_idxs
                       float* __restrict__ out)
{
    const int t    = threadIdx.x;           // 0..127 (one float4 per region)
    const int lane = t & 31;

    // ---- per-warp index-dtype detection (no extra kernel launch) ----
    // int64 buffer (values < 2048, little-endian): every odd 32-bit word is a
    // zero high half. int32 buffer: odd words are random j in [0,2048) —
    // P(all 64 samples zero) ~ 0. Both layouts have >= 8192 words.
    unsigned w0 = __ldg(&idxw[2 * lane + 1]);
    unsigned w1 = __ldg(&idxw[2 * (lane + 32) + 1]);
    const bool is64 = (__ballot_sync(0xffffffffu, (w0 | w1) != 0u) == 0u);

    const int span0 = blockIdx.x * NSP;
    const float4* __restrict__ f4 = reinterpret_cast<const float4*>(inp);
    float4* __restrict__ o4 = reinterpret_cast<float4*>(out);
    const float4 zero = make_float4(0.f, 0.f, 0.f, 0.f);

    // Per-span state: 32-bit element offsets (max offset 8.4M < 2^31)
    unsigned ofe[NSP], obs[NSP], ofp[NSP], obp[NSP], oout[NSP];
    bool skip[NSP], hpre[NSP], hpost[NSP];

    #pragma unroll
    for (int s = 0; s < NSP; s++) {
        const int span = span0 + s;
        const int b    = span >> 8;         // span / NS

        // Index values fit in the low 32-bit word under both layouts.
        int i, j;
        if (is64) {
            i = (int)idxw[4 * span + 0];
            j = (int)idxw[4 * span + 2];
        } else {
            i = (int)idxw[2 * span + 0];
            j = (int)idxw[2 * span + 1];
        }

        skip[s]  = (i == 0) && (j == 0);
        hpre[s]  = !skip[s] && (i >= 1);
        hpost[s] = !skip[s] && (j + 1 < Tc);

        // Safety clamp: garbage indices become wrong values, never faults.
        int ic = min(max(i, 0), Tc - 1);
        int jc = min(max(j, 0), Tc - 1);
        int ip = (ic >= 1) ? ic - 1 : 0;
        int jn = (jc + 1 < Tc) ? jc + 1 : Tc - 1;

        const unsigned base = (unsigned)b * (Tc * D4);
        ofe[s]  = base + (unsigned)jc * D4 + t;        // fwd[j]
        obs[s]  = base + (unsigned)ic * D4 + H4 + t;   // bwd[i]
        ofp[s]  = base + (unsigned)ip * D4 + t;        // fwd[i-1]
        obp[s]  = base + (unsigned)jn * D4 + H4 + t;   // bwd[j+1]
        oout[s] = (unsigned)span * (4 * H4) + t;       // output row base + t
    }

    // ---- batch all 8 independent LDG.128s before any compute/store ----
    float4 fe[NSP], bs[NSP], fp[NSP], bp[NSP];
    #pragma unroll
    for (int s = 0; s < NSP; s++) {
        fe[s] = skip[s]  ? zero : __ldg(&f4[ofe[s]]);
        bs[s] = skip[s]  ? zero : __ldg(&f4[obs[s]]);
        fp[s] = hpre[s]  ? __ldg(&f4[ofp[s]]) : zero;
        bp[s] = hpost[s] ? __ldg(&f4[obp[s]]) : zero;
    }

    // ---- compute + WRITE-THROUGH stores: output never allocates in L2, so
    //      the hot input read set stays L2-resident across graph replays ----
    #pragma unroll
    for (int s = 0; s < NSP; s++) {
        float4 r0 = make_float4(fe[s].x - fp[s].x, fe[s].y - fp[s].y,
                                fe[s].z - fp[s].z, fe[s].w - fp[s].w);
        float4 r1 = make_float4(bs[s].x - bp[s].x, bs[s].y - bp[s].y,
                                bs[s].z - bp[s].z, bs[s].w - bp[s].w);

        __stwt(&o4[oout[s]],          r0);      // f_end - f_pre
        __stwt(&o4[oout[s] + H4],     r1);      // b_start - b_post
        __stwt(&o4[oout[s] + 2 * H4], fp[s]);   // f_pre
        __stwt(&o4[oout[s] + 3 * H4], bp[s]);   // b_post
    }
}

extern "C" void kernel_launch(void* const* d_in, const int* in_sizes, int n_in,
                              void* d_out, int out_size)
{
    // Select inputs by element count, immune to ordering:
    // input: B*T*D = 33,554,432 elements; span_idxs: 8,192.
    int big   = (in_sizes[0] >= in_sizes[1]) ? 0 : 1;
    int small = 1 - big;

    const float*        inp  = (const float*)d_in[big];
    const unsigned int* idxs = (const unsigned int*)d_in[small];
    float*              out  = (float*)d_out;

    minus_span_kernel<<<NSPAN_TOT / NSP, 128>>>(inp, idxs, out);
}